// round 2
// baseline (speedup 1.0000x reference)
#include <cuda_runtime.h>
#include <cstdint>
#include <cstddef>

#define BB 8
#define SS 1024
#define EE 1024
#define HH 16
#define DD 64
#define NEG_INF (-3.402823466e38f)

// ---------------- scratch (no allocations allowed) ----------------
__device__ float g_Q[BB * SS * EE];
__device__ float g_K[BB * SS * EE];
__device__ float g_V[BB * SS * EE];
__device__ float g_Attn[BB * SS * EE];
__device__ float g_maskflag[BB * SS];   // 1.0f = padded (masked), 0.0f = keep
__device__ int   g_mask_dtype;          // 0=u8, 1=i32, 2=f32

// ---------------- key_padding_mask dtype detection ----------------
// Reads the first 8192 bytes (safe for every candidate encoding of 8192
// elements) and classifies: f32 (words are 0.0f/1.0f), i32 (words 0/1),
// or packed u8 bools (bytes 0/1 -> some word > 1 w.h.p.).
__global__ void detect_mask_kernel(const void* mask) {
    const unsigned int* w = (const unsigned int*)mask;
    __shared__ int s_f32, s_big;
    if (threadIdx.x == 0) { s_f32 = 0; s_big = 0; }
    __syncthreads();
    int lf = 0, lb = 0;
    for (int i = threadIdx.x; i < 2048; i += blockDim.x) {
        unsigned int v = w[i];
        if (v == 0x3F800000u) lf = 1;
        else if (v > 1u) lb = 1;
    }
    if (lf) atomicOr(&s_f32, 1);
    if (lb) atomicOr(&s_big, 1);
    __syncthreads();
    if (threadIdx.x == 0)
        g_mask_dtype = s_f32 ? 2 : (s_big ? 0 : 1);
}

__global__ void expand_mask_kernel(const void* mask) {
    int i = blockIdx.x * blockDim.x + threadIdx.x;
    if (i >= BB * SS) return;
    int dt = g_mask_dtype;
    bool f;
    if (dt == 0)      f = ((const unsigned char*)mask)[i] != 0;
    else if (dt == 1) f = ((const int*)mask)[i] != 0;
    else              f = ((const float*)mask)[i] != 0.0f;
    g_maskflag[i] = f ? 1.0f : 0.0f;
}

// ---------------- GEMM: C[M,N] = alpha*(A[M,K] @ W[N,K]^T + bias[N]) ----------------
// 128x64 block tile, 256 threads, 8x4 register tile, k-tile 16.
#define GM 128
#define GN 64
#define GK 16

__global__ __launch_bounds__(256) void gemm_bias_kernel(
    const float* __restrict__ A, const float* __restrict__ W,
    const float* __restrict__ bias, float* __restrict__ C,
    int M, int N, int K, float alpha)
{
    __shared__ float As[GK][GM + 4];   // transposed: [k][m]
    __shared__ float Ws[GK][GN + 4];   // transposed: [k][n]

    int tid = threadIdx.x;
    int tx = tid & 15;        // 0..15 -> n
    int ty = tid >> 4;        // 0..15 -> m
    int m0 = blockIdx.y * GM;
    int n0 = blockIdx.x * GN;

    float acc[8][4];
    #pragma unroll
    for (int i = 0; i < 8; ++i)
        #pragma unroll
        for (int j = 0; j < 4; ++j) acc[i][j] = 0.0f;

    int lkk = tid & 15;       // k within tile
    int lr  = tid >> 4;       // row group base

    for (int k0 = 0; k0 < K; k0 += GK) {
        #pragma unroll
        for (int it = 0; it < 8; ++it) {
            int m = lr + it * 16;
            As[lkk][m] = A[(size_t)(m0 + m) * K + k0 + lkk];
        }
        #pragma unroll
        for (int it = 0; it < 4; ++it) {
            int n = lr + it * 16;
            Ws[lkk][n] = W[(size_t)(n0 + n) * K + k0 + lkk];
        }
        __syncthreads();

        #pragma unroll
        for (int k = 0; k < GK; ++k) {
            float a[8], w[4];
            *(float4*)&a[0] = *(const float4*)&As[k][ty * 8];
            *(float4*)&a[4] = *(const float4*)&As[k][ty * 8 + 4];
            *(float4*)&w[0] = *(const float4*)&Ws[k][tx * 4];
            #pragma unroll
            for (int i = 0; i < 8; ++i)
                #pragma unroll
                for (int j = 0; j < 4; ++j)
                    acc[i][j] += a[i] * w[j];
        }
        __syncthreads();
    }

    float bv[4];
    *(float4*)&bv[0] = *(const float4*)&bias[n0 + tx * 4];
    #pragma unroll
    for (int i = 0; i < 8; ++i) {
        int row = m0 + ty * 8 + i;
        float4 r;
        r.x = alpha * (acc[i][0] + bv[0]);
        r.y = alpha * (acc[i][1] + bv[1]);
        r.z = alpha * (acc[i][2] + bv[2]);
        r.w = alpha * (acc[i][3] + bv[3]);
        *(float4*)&C[(size_t)row * N + n0 + tx * 4] = r;
    }
}

// ---------------- fused attention (flash-style) ----------------
// grid = (S/64, B*H), block = 256 (16x16). Each block: 64 query rows.
// Online softmax across 16 key tiles of 64. Bias + attn_mask + padding mask fused.
__global__ __launch_bounds__(256) void attention_kernel(
    const float* __restrict__ attn_bias,   // [B,H,S,S]
    const float* __restrict__ attn_mask)   // [S,S]
{
    __shared__ float Qs[DD][68];   // [d][qrow]
    __shared__ float Ks[DD][68];   // [d][kcol]
    __shared__ float Vs[64][68];   // [kcol][d]
    __shared__ float Ps[64][68];   // [kcol][qrow]

    int bh = blockIdx.y;
    int b = bh / HH, h = bh % HH;
    int q0 = blockIdx.x * 64;
    int tid = threadIdx.x;
    int tx = tid & 15;   // -> 4 key cols / 4 out dims
    int ty = tid >> 4;   // -> 4 query rows

    // load Q tile (transposed into [d][m])
    #pragma unroll
    for (int it = 0; it < 4; ++it) {
        int idx = tid + it * 256;
        int r = idx >> 4;
        int c4 = (idx & 15) * 4;
        float4 q = *(const float4*)&g_Q[(size_t)(b * SS + q0 + r) * EE + h * DD + c4];
        Qs[c4][r] = q.x; Qs[c4 + 1][r] = q.y; Qs[c4 + 2][r] = q.z; Qs[c4 + 3][r] = q.w;
    }

    float o[4][4];
    float m_r[4], l_r[4];
    #pragma unroll
    for (int i = 0; i < 4; ++i) {
        m_r[i] = -INFINITY; l_r[i] = 0.0f;
        #pragma unroll
        for (int j = 0; j < 4; ++j) o[i][j] = 0.0f;
    }
    __syncthreads();

    for (int k0 = 0; k0 < SS; k0 += 64) {
        // load K (transposed) and V tiles
        #pragma unroll
        for (int it = 0; it < 4; ++it) {
            int idx = tid + it * 256;
            int r = idx >> 4;
            int c4 = (idx & 15) * 4;
            size_t base = (size_t)(b * SS + k0 + r) * EE + h * DD + c4;
            float4 kv = *(const float4*)&g_K[base];
            Ks[c4][r] = kv.x; Ks[c4 + 1][r] = kv.y; Ks[c4 + 2][r] = kv.z; Ks[c4 + 3][r] = kv.w;
            float4 vv = *(const float4*)&g_V[base];
            *(float4*)&Vs[r][c4] = vv;
        }
        __syncthreads();

        // scores s[4][4] = Q . K^T
        float s[4][4];
        #pragma unroll
        for (int i = 0; i < 4; ++i)
            #pragma unroll
            for (int j = 0; j < 4; ++j) s[i][j] = 0.0f;

        #pragma unroll 8
        for (int d = 0; d < DD; ++d) {
            float a[4], kq[4];
            *(float4*)&a[0]  = *(const float4*)&Qs[d][ty * 4];
            *(float4*)&kq[0] = *(const float4*)&Ks[d][tx * 4];
            #pragma unroll
            for (int i = 0; i < 4; ++i)
                #pragma unroll
                for (int j = 0; j < 4; ++j)
                    s[i][j] += a[i] * kq[j];
        }

        // bias + attn_mask + key padding mask (where -> NEG_INF)
        float mf[4];
        *(float4*)&mf[0] = *(const float4*)&g_maskflag[b * SS + k0 + tx * 4];

        #pragma unroll
        for (int i = 0; i < 4; ++i) {
            int qr = q0 + ty * 4 + i;
            float bia[4], am[4];
            *(float4*)&bia[0] = *(const float4*)&attn_bias[((size_t)(b * HH + h) * SS + qr) * SS + k0 + tx * 4];
            *(float4*)&am[0]  = *(const float4*)&attn_mask[(size_t)qr * SS + k0 + tx * 4];
            #pragma unroll
            for (int j = 0; j < 4; ++j) {
                float v = s[i][j] + bia[j] + am[j];
                s[i][j] = (mf[j] > 0.5f) ? NEG_INF : v;
            }
        }

        // online softmax + write P (transposed)
        #pragma unroll
        for (int i = 0; i < 4; ++i) {
            float mx = fmaxf(fmaxf(s[i][0], s[i][1]), fmaxf(s[i][2], s[i][3]));
            #pragma unroll
            for (int off = 1; off < 16; off <<= 1)
                mx = fmaxf(mx, __shfl_xor_sync(0xffffffffu, mx, off));
            float m_new = fmaxf(m_r[i], mx);
            float scale = __expf(m_r[i] - m_new);
            float p[4], rs = 0.0f;
            #pragma unroll
            for (int j = 0; j < 4; ++j) { p[j] = __expf(s[i][j] - m_new); rs += p[j]; }
            #pragma unroll
            for (int off = 1; off < 16; off <<= 1)
                rs += __shfl_xor_sync(0xffffffffu, rs, off);
            l_r[i] = l_r[i] * scale + rs;
            m_r[i] = m_new;
            #pragma unroll
            for (int j = 0; j < 4; ++j) o[i][j] *= scale;
            #pragma unroll
            for (int j = 0; j < 4; ++j)
                Ps[tx * 4 + j][ty * 4 + i] = p[j];
        }
        __syncthreads();

        // O += P @ V
        #pragma unroll 8
        for (int jj = 0; jj < 64; ++jj) {
            float p[4], v[4];
            *(float4*)&p[0] = *(const float4*)&Ps[jj][ty * 4];
            *(float4*)&v[0] = *(const float4*)&Vs[jj][tx * 4];
            #pragma unroll
            for (int i = 0; i < 4; ++i)
                #pragma unroll
                for (int j = 0; j < 4; ++j)
                    o[i][j] += p[i] * v[j];
        }
        __syncthreads();
    }

    // normalize + store to attn scratch in [B,S,H*D] layout
    #pragma unroll
    for (int i = 0; i < 4; ++i) {
        float inv = 1.0f / l_r[i];
        float4 r;
        r.x = o[i][0] * inv; r.y = o[i][1] * inv;
        r.z = o[i][2] * inv; r.w = o[i][3] * inv;
        *(float4*)&g_Attn[(size_t)(b * SS + q0 + ty * 4 + i) * EE + h * DD + tx * 4] = r;
    }
}

// ---------------- launch ----------------
extern "C" void kernel_launch(void* const* d_in, const int* in_sizes, int n_in,
                              void* d_out, int out_size) {
    const float* query     = (const float*)d_in[0];
    // d_in[1]=key, d_in[2]=value unused (self-attention: all projections from query)
    const float* attn_bias = (const float*)d_in[3];
    const void*  kpm       = d_in[4];
    const float* attn_mask = (const float*)d_in[5];
    const float* Wq = (const float*)d_in[9];
    const float* bq = (const float*)d_in[10];
    const float* Wk = (const float*)d_in[11];
    const float* bk = (const float*)d_in[12];
    const float* Wv = (const float*)d_in[13];
    const float* bv = (const float*)d_in[14];
    const float* Wo = (const float*)d_in[15];
    const float* bo = (const float*)d_in[16];
    float* out = (float*)d_out;

    float *gQ, *gK, *gV, *gA;
    cudaGetSymbolAddress((void**)&gQ, g_Q);
    cudaGetSymbolAddress((void**)&gK, g_K);
    cudaGetSymbolAddress((void**)&gV, g_V);
    cudaGetSymbolAddress((void**)&gA, g_Attn);

    detect_mask_kernel<<<1, 256>>>(kpm);
    expand_mask_kernel<<<(BB * SS + 255) / 256, 256>>>(kpm);

    const int M = BB * SS;   // 8192
    dim3 ggrid(EE / GN, M / GM);   // (16, 64)
    const float scaling = 0.125f;  // D^-0.5

    gemm_bias_kernel<<<ggrid, 256>>>(query, Wq, bq, gQ, M, EE, EE, scaling);
    gemm_bias_kernel<<<ggrid, 256>>>(query, Wk, bk, gK, M, EE, EE, 1.0f);
    gemm_bias_kernel<<<ggrid, 256>>>(query, Wv, bv, gV, M, EE, EE, 1.0f);

    attention_kernel<<<dim3(SS / 64, BB * HH), 256>>>(attn_bias, attn_mask);

    gemm_bias_kernel<<<ggrid, 256>>>(gA, Wo, bo, out, M, EE, EE, 1.0f);
}

// round 6
// speedup vs baseline: 1.5473x; 1.5473x over previous
#include <cuda_runtime.h>
#include <cuda_bf16.h>
#include <cstdint>
#include <cstddef>

#define BB 8
#define SS 1024
#define EE 1024
#define HH 16
#define DD 64
#define NEG_INF (-3.402823466e38f)

// ---------------- scratch (no allocations allowed) ----------------
__device__ float g_Q[BB * SS * EE];
__device__ float g_K[BB * SS * EE];
__device__ float g_V[BB * SS * EE];
__device__ __nv_bfloat16 g_Xhi[BB * SS * EE];   // query split
__device__ __nv_bfloat16 g_Xlo[BB * SS * EE];
__device__ __nv_bfloat16 g_AThi[BB * SS * EE];  // attention output split
__device__ __nv_bfloat16 g_ATlo[BB * SS * EE];
__device__ __nv_bfloat16 g_Whi[4][EE * EE];     // Wq,Wk,Wv,Wo splits
__device__ __nv_bfloat16 g_Wlo[4][EE * EE];
__device__ float g_maskflag[BB * SS];
__device__ int   g_mask_dtype;

// ---------------- helpers ----------------
__device__ __forceinline__ uint32_t smem_u32(const void* p) {
    uint32_t a;
    asm("{ .reg .u64 t; cvta.to.shared.u64 t, %1; cvt.u32.u64 %0, t; }" : "=r"(a) : "l"(p));
    return a;
}

__device__ __forceinline__ void ldsm4(uint32_t* r, uint32_t addr) {
    asm volatile("ldmatrix.sync.aligned.m8n8.x4.shared.b16 {%0,%1,%2,%3}, [%4];"
        : "=r"(r[0]), "=r"(r[1]), "=r"(r[2]), "=r"(r[3]) : "r"(addr));
}

__device__ __forceinline__ void mma16816(float* c, const uint32_t* a, uint32_t b0, uint32_t b1) {
    asm volatile(
        "mma.sync.aligned.m16n8k16.row.col.f32.bf16.bf16.f32 "
        "{%0,%1,%2,%3}, {%4,%5,%6,%7}, {%8,%9}, {%0,%1,%2,%3};"
        : "+f"(c[0]), "+f"(c[1]), "+f"(c[2]), "+f"(c[3])
        : "r"(a[0]), "r"(a[1]), "r"(a[2]), "r"(a[3]), "r"(b0), "r"(b1));
}

// ---------------- fp32 -> bf16 hi/lo split ----------------
__global__ void split_kernel(const float* __restrict__ src,
                             __nv_bfloat16* __restrict__ hi,
                             __nv_bfloat16* __restrict__ lo, int n4) {
    int i = blockIdx.x * blockDim.x + threadIdx.x;
    if (i >= n4) return;
    float4 v = ((const float4*)src)[i];
    float vv[4] = {v.x, v.y, v.z, v.w};
    __nv_bfloat16 h[4], l[4];
    #pragma unroll
    for (int j = 0; j < 4; ++j) {
        h[j] = __float2bfloat16(vv[j]);
        l[j] = __float2bfloat16(vv[j] - __bfloat162float(h[j]));
    }
    __nv_bfloat162* ph = (__nv_bfloat162*)&hi[(size_t)i * 4];
    __nv_bfloat162* pl = (__nv_bfloat162*)&lo[(size_t)i * 4];
    ph[0] = __halves2bfloat162(h[0], h[1]);
    ph[1] = __halves2bfloat162(h[2], h[3]);
    pl[0] = __halves2bfloat162(l[0], l[1]);
    pl[1] = __halves2bfloat162(l[2], l[3]);
}

// ---------------- key_padding_mask dtype detection ----------------
__global__ void detect_mask_kernel(const void* mask) {
    const unsigned int* w = (const unsigned int*)mask;
    __shared__ int s_f32, s_big;
    if (threadIdx.x == 0) { s_f32 = 0; s_big = 0; }
    __syncthreads();
    int lf = 0, lb = 0;
    for (int i = threadIdx.x; i < 2048; i += blockDim.x) {
        unsigned int v = w[i];
        if (v == 0x3F800000u) lf = 1;
        else if (v > 1u) lb = 1;
    }
    if (lf) atomicOr(&s_f32, 1);
    if (lb) atomicOr(&s_big, 1);
    __syncthreads();
    if (threadIdx.x == 0)
        g_mask_dtype = s_f32 ? 2 : (s_big ? 0 : 1);
}

__global__ void expand_mask_kernel(const void* mask) {
    int i = blockIdx.x * blockDim.x + threadIdx.x;
    if (i >= BB * SS) return;
    int dt = g_mask_dtype;
    bool f;
    if (dt == 0)      f = ((const unsigned char*)mask)[i] != 0;
    else if (dt == 1) f = ((const int*)mask)[i] != 0;
    else              f = ((const float*)mask)[i] != 0.0f;
    g_maskflag[i] = f ? 1.0f : 0.0f;
}

// ---------------- mma.sync GEMM: C[M,N] = alpha*(A@W^T + bias) ----------------
// A = Ahi+Alo [M,K] bf16, W = Whi+Wlo [N,K] bf16 -> 3-term split product.
// CTA tile 128x128, 8 warps (2x4), warp tile 64x32, K-chunk 32.
// smem rows padded to 80B -> ldmatrix conflict-free (banks 20r mod 32 distinct).
#define KC 32
#define TS 80                       // bytes per smem row
#define SM_A_HI 0
#define SM_A_LO 10240
#define SM_B_HI 20480
#define SM_B_LO 30720

__global__ __launch_bounds__(256, 2)
void gemm_mma_kernel(const __nv_bfloat16* __restrict__ Ahi,
                     const __nv_bfloat16* __restrict__ Alo,
                     const __nv_bfloat16* __restrict__ Whi,
                     const __nv_bfloat16* __restrict__ Wlo,
                     const float* __restrict__ bias,
                     float* __restrict__ C, float alpha)
{
    __shared__ __align__(16) char smem[40960];
    int tid = threadIdx.x;
    int wid = tid >> 5;
    int lane = tid & 31;
    int m0 = blockIdx.y * 128;
    int n0 = blockIdx.x * 128;
    int wm = wid & 1;        // 2 M slots of 64
    int wn = wid >> 1;       // 4 N slots of 32

    float acc[4][4][4];
    #pragma unroll
    for (int mt = 0; mt < 4; ++mt)
        #pragma unroll
        for (int nt = 0; nt < 4; ++nt)
            #pragma unroll
            for (int k = 0; k < 4; ++k) acc[mt][nt][k] = 0.0f;

    // ldmatrix lane address bases (constant across chunks; single-stage smem)
    uint32_t sb = smem_u32(smem);
    int lr = lane & 7;
    int qq = lane >> 3;           // which 8x8 matrix this lane addresses
    uint32_t aHiA[4], aLoA[4], bHiA[2], bLoA[2];
    #pragma unroll
    for (int mt = 0; mt < 4; ++mt) {
        int row = wm * 64 + mt * 16 + lr + (qq & 1) * 8;
        uint32_t off = row * TS + (qq >> 1) * 16;
        aHiA[mt] = sb + SM_A_HI + off;
        aLoA[mt] = sb + SM_A_LO + off;
    }
    #pragma unroll
    for (int p = 0; p < 2; ++p) {
        int row = wn * 32 + p * 16 + lr + (qq & 1) * 8;
        uint32_t off = row * TS + (qq >> 1) * 16;
        bHiA[p] = sb + SM_B_HI + off;
        bLoA[p] = sb + SM_B_LO + off;
    }

    // global load indices
    int glr = tid >> 2;          // 0..63 (row block, +256/4=64 per iter)
    int glj = tid & 3;           // 16B quad within 64B row

    for (int c = 0; c < EE / KC; ++c) {
        int kc = c * KC;
        #pragma unroll
        for (int it = 0; it < 2; ++it) {
            int r = glr + it * 64;
            uint32_t so = r * TS + glj * 16;
            size_t ga = (size_t)(m0 + r) * EE + kc + glj * 8;
            size_t gb = (size_t)(n0 + r) * EE + kc + glj * 8;
            *(uint4*)(smem + SM_A_HI + so) = *(const uint4*)(Ahi + ga);
            *(uint4*)(smem + SM_A_LO + so) = *(const uint4*)(Alo + ga);
            *(uint4*)(smem + SM_B_HI + so) = *(const uint4*)(Whi + gb);
            *(uint4*)(smem + SM_B_LO + so) = *(const uint4*)(Wlo + gb);
        }
        __syncthreads();

        #pragma unroll
        for (int ks = 0; ks < 2; ++ks) {
            uint32_t koB = ks * 32;   // 16 bf16 = 32 bytes
            uint32_t aH[4][4], bH[2][4];
            #pragma unroll
            for (int mt = 0; mt < 4; ++mt) ldsm4(aH[mt], aHiA[mt] + koB);
            #pragma unroll
            for (int p = 0; p < 2; ++p) ldsm4(bH[p], bHiA[p] + koB);
            // pass 1: A_hi * B_hi
            #pragma unroll
            for (int mt = 0; mt < 4; ++mt)
                #pragma unroll
                for (int nt = 0; nt < 4; ++nt)
                    mma16816(acc[mt][nt], aH[mt], bH[nt >> 1][nt & 1], bH[nt >> 1][(nt & 1) + 2]);
            // pass 2: A_hi * B_lo
            {
                uint32_t bL[2][4];
                #pragma unroll
                for (int p = 0; p < 2; ++p) ldsm4(bL[p], bLoA[p] + koB);
                #pragma unroll
                for (int mt = 0; mt < 4; ++mt)
                    #pragma unroll
                    for (int nt = 0; nt < 4; ++nt)
                        mma16816(acc[mt][nt], aH[mt], bL[nt >> 1][nt & 1], bL[nt >> 1][(nt & 1) + 2]);
            }
            // pass 3: A_lo * B_hi
            {
                uint32_t aL[4][4];
                #pragma unroll
                for (int mt = 0; mt < 4; ++mt) ldsm4(aL[mt], aLoA[mt] + koB);
                #pragma unroll
                for (int mt = 0; mt < 4; ++mt)
                    #pragma unroll
                    for (int nt = 0; nt < 4; ++nt)
                        mma16816(acc[mt][nt], aL[mt], bH[nt >> 1][nt & 1], bH[nt >> 1][(nt & 1) + 2]);
            }
        }
        __syncthreads();
    }

    // epilogue: fragment regs -> global with fused bias + alpha
    int gid = lane >> 2;
    int tig = lane & 3;
    #pragma unroll
    for (int nt = 0; nt < 4; ++nt) {
        int col = n0 + wn * 32 + nt * 8 + tig * 2;
        float b0 = bias[col], b1 = bias[col + 1];
        #pragma unroll
        for (int mt = 0; mt < 4; ++mt) {
            int row = m0 + wm * 64 + mt * 16 + gid;
            float2 v0, v1;
            v0.x = alpha * (acc[mt][nt][0] + b0);
            v0.y = alpha * (acc[mt][nt][1] + b1);
            v1.x = alpha * (acc[mt][nt][2] + b0);
            v1.y = alpha * (acc[mt][nt][3] + b1);
            *(float2*)&C[(size_t)row * EE + col] = v0;
            *(float2*)&C[(size_t)(row + 8) * EE + col] = v1;
        }
    }
}

// ---------------- fused attention (flash-style, SIMT fp32) ----------------
__global__ __launch_bounds__(256) void attention_kernel(
    const float* __restrict__ attn_bias,   // [B,H,S,S]
    const float* __restrict__ attn_mask)   // [S,S]
{
    __shared__ float Qs[DD][68];
    __shared__ float Ks[DD][68];
    __shared__ float Vs[64][68];
    __shared__ float Ps[64][68];

    int bh = blockIdx.y;
    int b = bh / HH, h = bh % HH;
    int q0 = blockIdx.x * 64;
    int tid = threadIdx.x;
    int tx = tid & 15;
    int ty = tid >> 4;

    #pragma unroll
    for (int it = 0; it < 4; ++it) {
        int idx = tid + it * 256;
        int r = idx >> 4;
        int c4 = (idx & 15) * 4;
        float4 q = *(const float4*)&g_Q[(size_t)(b * SS + q0 + r) * EE + h * DD + c4];
        Qs[c4][r] = q.x; Qs[c4 + 1][r] = q.y; Qs[c4 + 2][r] = q.z; Qs[c4 + 3][r] = q.w;
    }

    float o[4][4];
    float m_r[4], l_r[4];
    #pragma unroll
    for (int i = 0; i < 4; ++i) {
        m_r[i] = -INFINITY; l_r[i] = 0.0f;
        #pragma unroll
        for (int j = 0; j < 4; ++j) o[i][j] = 0.0f;
    }
    __syncthreads();

    for (int k0 = 0; k0 < SS; k0 += 64) {
        #pragma unroll
        for (int it = 0; it < 4; ++it) {
            int idx = tid + it * 256;
            int r = idx >> 4;
            int c4 = (idx & 15) * 4;
            size_t base = (size_t)(b * SS + k0 + r) * EE + h * DD + c4;
            float4 kv = *(const float4*)&g_K[base];
            Ks[c4][r] = kv.x; Ks[c4 + 1][r] = kv.y; Ks[c4 + 2][r] = kv.z; Ks[c4 + 3][r] = kv.w;
            float4 vv = *(const float4*)&g_V[base];
            *(float4*)&Vs[r][c4] = vv;
        }
        __syncthreads();

        float s[4][4];
        #pragma unroll
        for (int i = 0; i < 4; ++i)
            #pragma unroll
            for (int j = 0; j < 4; ++j) s[i][j] = 0.0f;

        #pragma unroll 8
        for (int d = 0; d < DD; ++d) {
            float a[4], kq[4];
            *(float4*)&a[0]  = *(const float4*)&Qs[d][ty * 4];
            *(float4*)&kq[0] = *(const float4*)&Ks[d][tx * 4];
            #pragma unroll
            for (int i = 0; i < 4; ++i)
                #pragma unroll
                for (int j = 0; j < 4; ++j)
                    s[i][j] += a[i] * kq[j];
        }

        float mf[4];
        *(float4*)&mf[0] = *(const float4*)&g_maskflag[b * SS + k0 + tx * 4];

        #pragma unroll
        for (int i = 0; i < 4; ++i) {
            int qr = q0 + ty * 4 + i;
            float bia[4], am[4];
            *(float4*)&bia[0] = *(const float4*)&attn_bias[((size_t)(b * HH + h) * SS + qr) * SS + k0 + tx * 4];
            *(float4*)&am[0]  = *(const float4*)&attn_mask[(size_t)qr * SS + k0 + tx * 4];
            #pragma unroll
            for (int j = 0; j < 4; ++j) {
                float v = s[i][j] + bia[j] + am[j];
                s[i][j] = (mf[j] > 0.5f) ? NEG_INF : v;
            }
        }

        #pragma unroll
        for (int i = 0; i < 4; ++i) {
            float mx = fmaxf(fmaxf(s[i][0], s[i][1]), fmaxf(s[i][2], s[i][3]));
            #pragma unroll
            for (int off = 1; off < 16; off <<= 1)
                mx = fmaxf(mx, __shfl_xor_sync(0xffffffffu, mx, off));
            float m_new = fmaxf(m_r[i], mx);
            float scale = __expf(m_r[i] - m_new);
            float p[4], rs = 0.0f;
            #pragma unroll
            for (int j = 0; j < 4; ++j) { p[j] = __expf(s[i][j] - m_new); rs += p[j]; }
            #pragma unroll
            for (int off = 1; off < 16; off <<= 1)
                rs += __shfl_xor_sync(0xffffffffu, rs, off);
            l_r[i] = l_r[i] * scale + rs;
            m_r[i] = m_new;
            #pragma unroll
            for (int j = 0; j < 4; ++j) o[i][j] *= scale;
            #pragma unroll
            for (int j = 0; j < 4; ++j)
                Ps[tx * 4 + j][ty * 4 + i] = p[j];
        }
        __syncthreads();

        #pragma unroll 8
        for (int jj = 0; jj < 64; ++jj) {
            float p[4], v[4];
            *(float4*)&p[0] = *(const float4*)&Ps[jj][ty * 4];
            *(float4*)&v[0] = *(const float4*)&Vs[jj][tx * 4];
            #pragma unroll
            for (int i = 0; i < 4; ++i)
                #pragma unroll
                for (int j = 0; j < 4; ++j)
                    o[i][j] += p[i] * v[j];
        }
        __syncthreads();
    }

    // normalize + emit bf16 hi/lo split for the output projection GEMM
    #pragma unroll
    for (int i = 0; i < 4; ++i) {
        float inv = 1.0f / l_r[i];
        size_t idx = (size_t)(b * SS + q0 + ty * 4 + i) * EE + h * DD + tx * 4;
        __nv_bfloat16 h4[4], l4[4];
        #pragma unroll
        for (int j = 0; j < 4; ++j) {
            float v = o[i][j] * inv;
            h4[j] = __float2bfloat16(v);
            l4[j] = __float2bfloat16(v - __bfloat162float(h4[j]));
        }
        __nv_bfloat162* ph = (__nv_bfloat162*)&g_AThi[idx];
        __nv_bfloat162* pl = (__nv_bfloat162*)&g_ATlo[idx];
        ph[0] = __halves2bfloat162(h4[0], h4[1]);
        ph[1] = __halves2bfloat162(h4[2], h4[3]);
        pl[0] = __halves2bfloat162(l4[0], l4[1]);
        pl[1] = __halves2bfloat162(l4[2], l4[3]);
    }
}

// ---------------- launch ----------------
extern "C" void kernel_launch(void* const* d_in, const int* in_sizes, int n_in,
                              void* d_out, int out_size) {
    const float* query     = (const float*)d_in[0];
    const float* attn_bias = (const float*)d_in[3];
    const void*  kpm       = d_in[4];
    const float* attn_mask = (const float*)d_in[5];
    const float* Wq = (const float*)d_in[9];
    const float* bq = (const float*)d_in[10];
    const float* Wk = (const float*)d_in[11];
    const float* bk = (const float*)d_in[12];
    const float* Wv = (const float*)d_in[13];
    const float* bv = (const float*)d_in[14];
    const float* Wo = (const float*)d_in[15];
    const float* bo = (const float*)d_in[16];
    float* out = (float*)d_out;

    float *gQ, *gK, *gV;
    __nv_bfloat16 *gXhi, *gXlo, *gAThi, *gATlo, *gWhi, *gWlo;
    cudaGetSymbolAddress((void**)&gQ, g_Q);
    cudaGetSymbolAddress((void**)&gK, g_K);
    cudaGetSymbolAddress((void**)&gV, g_V);
    cudaGetSymbolAddress((void**)&gXhi, g_Xhi);
    cudaGetSymbolAddress((void**)&gXlo, g_Xlo);
    cudaGetSymbolAddress((void**)&gAThi, g_AThi);
    cudaGetSymbolAddress((void**)&gATlo, g_ATlo);
    cudaGetSymbolAddress((void**)&gWhi, g_Whi);
    cudaGetSymbolAddress((void**)&gWlo, g_Wlo);

    // splits
    const int nq4 = BB * SS * EE / 4;
    const int nw4 = EE * EE / 4;
    split_kernel<<<(nq4 + 255) / 256, 256>>>(query, gXhi, gXlo, nq4);
    split_kernel<<<(nw4 + 255) / 256, 256>>>(Wq, gWhi + 0 * (size_t)EE * EE, gWlo + 0 * (size_t)EE * EE, nw4);
    split_kernel<<<(nw4 + 255) / 256, 256>>>(Wk, gWhi + 1 * (size_t)EE * EE, gWlo + 1 * (size_t)EE * EE, nw4);
    split_kernel<<<(nw4 + 255) / 256, 256>>>(Wv, gWhi + 2 * (size_t)EE * EE, gWlo + 2 * (size_t)EE * EE, nw4);
    split_kernel<<<(nw4 + 255) / 256, 256>>>(Wo, gWhi + 3 * (size_t)EE * EE, gWlo + 3 * (size_t)EE * EE, nw4);

    detect_mask_kernel<<<1, 256>>>(kpm);
    expand_mask_kernel<<<(BB * SS + 255) / 256, 256>>>(kpm);

    dim3 ggrid(EE / 128, BB * SS / 128);   // (8, 64)
    const float scaling = 0.125f;          // D^-0.5

    gemm_mma_kernel<<<ggrid, 256>>>(gXhi, gXlo,
        gWhi + 0 * (size_t)EE * EE, gWlo + 0 * (size_t)EE * EE, bq, gQ, scaling);
    gemm_mma_kernel<<<ggrid, 256>>>(gXhi, gXlo,
        gWhi + 1 * (size_t)EE * EE, gWlo + 1 * (size_t)EE * EE, bk, gK, 1.0f);
    gemm_mma_kernel<<<ggrid, 256>>>(gXhi, gXlo,
        gWhi + 2 * (size_t)EE * EE, gWlo + 2 * (size_t)EE * EE, bv, gV, 1.0f);

    attention_kernel<<<dim3(SS / 64, BB * HH), 256>>>(attn_bias, attn_mask);

    gemm_mma_kernel<<<ggrid, 256>>>(gAThi, gATlo,
        gWhi + 3 * (size_t)EE * EE, gWlo + 3 * (size_t)EE * EE, bo, out, 1.0f);
}

// round 8
// speedup vs baseline: 1.7481x; 1.1298x over previous
#include <cuda_runtime.h>
#include <cuda_bf16.h>
#include <cstdint>
#include <cstddef>

#define BB 8
#define SS 1024
#define EE 1024
#define HH 16
#define DD 64
#define NEG_INF (-3.402823466e38f)

// ---------------- scratch (no allocations allowed) ----------------
__device__ __nv_bfloat16 g_Xhi[BB * SS * EE];   // query split
__device__ __nv_bfloat16 g_Xlo[BB * SS * EE];
__device__ __nv_bfloat16 g_Qhi[BB * SS * EE];   // projected q/k/v splits
__device__ __nv_bfloat16 g_Qlo[BB * SS * EE];
__device__ __nv_bfloat16 g_Khi[BB * SS * EE];
__device__ __nv_bfloat16 g_Klo[BB * SS * EE];
__device__ __nv_bfloat16 g_Vhi[BB * SS * EE];
__device__ __nv_bfloat16 g_Vlo[BB * SS * EE];
__device__ __nv_bfloat16 g_AThi[BB * SS * EE];  // attention output split
__device__ __nv_bfloat16 g_ATlo[BB * SS * EE];
__device__ __nv_bfloat16 g_Whi[4][EE * EE];     // Wq,Wk,Wv,Wo splits
__device__ __nv_bfloat16 g_Wlo[4][EE * EE];
__device__ float g_maskflag[BB * SS];
__device__ int   g_mask_dtype;

// ---------------- helpers ----------------
__device__ __forceinline__ uint32_t smem_u32(const void* p) {
    uint32_t a;
    asm("{ .reg .u64 t; cvta.to.shared.u64 t, %1; cvt.u32.u64 %0, t; }" : "=r"(a) : "l"(p));
    return a;
}
__device__ __forceinline__ void ldsm4(uint32_t* r, uint32_t addr) {
    asm volatile("ldmatrix.sync.aligned.m8n8.x4.shared.b16 {%0,%1,%2,%3}, [%4];"
        : "=r"(r[0]), "=r"(r[1]), "=r"(r[2]), "=r"(r[3]) : "r"(addr));
}
__device__ __forceinline__ void ldsm4t(uint32_t* r, uint32_t addr) {
    asm volatile("ldmatrix.sync.aligned.m8n8.x4.trans.shared.b16 {%0,%1,%2,%3}, [%4];"
        : "=r"(r[0]), "=r"(r[1]), "=r"(r[2]), "=r"(r[3]) : "r"(addr));
}
__device__ __forceinline__ void mma16816(float* c, const uint32_t* a, uint32_t b0, uint32_t b1) {
    asm volatile(
        "mma.sync.aligned.m16n8k16.row.col.f32.bf16.bf16.f32 "
        "{%0,%1,%2,%3}, {%4,%5,%6,%7}, {%8,%9}, {%0,%1,%2,%3};"
        : "+f"(c[0]), "+f"(c[1]), "+f"(c[2]), "+f"(c[3])
        : "r"(a[0]), "r"(a[1]), "r"(a[2]), "r"(a[3]), "r"(b0), "r"(b1));
}
__device__ __forceinline__ uint32_t pack_hi2(float x, float y) {
    __nv_bfloat162 v = __halves2bfloat162(__float2bfloat16(x), __float2bfloat16(y));
    return *(uint32_t*)&v;
}
__device__ __forceinline__ uint32_t pack_lo2(float x, float y, uint32_t hi) {
    __nv_bfloat162 h = *(__nv_bfloat162*)&hi;
    __nv_bfloat162 v = __halves2bfloat162(
        __float2bfloat16(x - __bfloat162float(h.x)),
        __float2bfloat16(y - __bfloat162float(h.y)));
    return *(uint32_t*)&v;
}

// ---------------- fp32 -> bf16 hi/lo split ----------------
__global__ void split_kernel(const float* __restrict__ src,
                             __nv_bfloat16* __restrict__ hi,
                             __nv_bfloat16* __restrict__ lo, int n4) {
    int i = blockIdx.x * blockDim.x + threadIdx.x;
    if (i >= n4) return;
    float4 v = ((const float4*)src)[i];
    float vv[4] = {v.x, v.y, v.z, v.w};
    __nv_bfloat16 h[4], l[4];
    #pragma unroll
    for (int j = 0; j < 4; ++j) {
        h[j] = __float2bfloat16(vv[j]);
        l[j] = __float2bfloat16(vv[j] - __bfloat162float(h[j]));
    }
    __nv_bfloat162* ph = (__nv_bfloat162*)&hi[(size_t)i * 4];
    __nv_bfloat162* pl = (__nv_bfloat162*)&lo[(size_t)i * 4];
    ph[0] = __halves2bfloat162(h[0], h[1]);
    ph[1] = __halves2bfloat162(h[2], h[3]);
    pl[0] = __halves2bfloat162(l[0], l[1]);
    pl[1] = __halves2bfloat162(l[2], l[3]);
}

// ---------------- key_padding_mask dtype detection ----------------
__global__ void detect_mask_kernel(const void* mask) {
    const unsigned int* w = (const unsigned int*)mask;
    __shared__ int s_f32, s_big;
    if (threadIdx.x == 0) { s_f32 = 0; s_big = 0; }
    __syncthreads();
    int lf = 0, lb = 0;
    for (int i = threadIdx.x; i < 2048; i += blockDim.x) {
        unsigned int v = w[i];
        if (v == 0x3F800000u) lf = 1;
        else if (v > 1u) lb = 1;
    }
    if (lf) atomicOr(&s_f32, 1);
    if (lb) atomicOr(&s_big, 1);
    __syncthreads();
    if (threadIdx.x == 0)
        g_mask_dtype = s_f32 ? 2 : (s_big ? 0 : 1);
}

__global__ void expand_mask_kernel(const void* mask) {
    int i = blockIdx.x * blockDim.x + threadIdx.x;
    if (i >= BB * SS) return;
    int dt = g_mask_dtype;
    bool f;
    if (dt == 0)      f = ((const unsigned char*)mask)[i] != 0;
    else if (dt == 1) f = ((const int*)mask)[i] != 0;
    else              f = ((const float*)mask)[i] != 0.0f;
    g_maskflag[i] = f ? 1.0f : 0.0f;
}

// ---------------- mma.sync GEMM: C = alpha*(A@W^T + bias) ----------------
// 3-term bf16 split product, CTA 128x128, 8 warps, warp tile 64x32, K-chunk 32.
// SPLIT=true: emit bf16 hi/lo split instead of fp32.
#define KC 32
#define TS 80
#define SM_A_HI 0
#define SM_A_LO 10240
#define SM_B_HI 20480
#define SM_B_LO 30720

template <bool SPLIT>
__global__ __launch_bounds__(256, 2)
void gemm_mma_kernel(const __nv_bfloat16* __restrict__ Ahi,
                     const __nv_bfloat16* __restrict__ Alo,
                     const __nv_bfloat16* __restrict__ Whi,
                     const __nv_bfloat16* __restrict__ Wlo,
                     const float* __restrict__ bias,
                     float* __restrict__ C,
                     __nv_bfloat16* __restrict__ Chi,
                     __nv_bfloat16* __restrict__ Clo,
                     float alpha)
{
    __shared__ __align__(16) char smem[40960];
    int tid = threadIdx.x;
    int wid = tid >> 5;
    int lane = tid & 31;
    int m0 = blockIdx.y * 128;
    int n0 = blockIdx.x * 128;
    int wm = wid & 1;
    int wn = wid >> 1;

    float acc[4][4][4];
    #pragma unroll
    for (int mt = 0; mt < 4; ++mt)
        #pragma unroll
        for (int nt = 0; nt < 4; ++nt)
            #pragma unroll
            for (int k = 0; k < 4; ++k) acc[mt][nt][k] = 0.0f;

    uint32_t sb = smem_u32(smem);
    int lr = lane & 7;
    int qq = lane >> 3;
    uint32_t aHiA[4], aLoA[4], bHiA[2], bLoA[2];
    #pragma unroll
    for (int mt = 0; mt < 4; ++mt) {
        int row = wm * 64 + mt * 16 + lr + (qq & 1) * 8;
        uint32_t off = row * TS + (qq >> 1) * 16;
        aHiA[mt] = sb + SM_A_HI + off;
        aLoA[mt] = sb + SM_A_LO + off;
    }
    #pragma unroll
    for (int p = 0; p < 2; ++p) {
        int row = wn * 32 + p * 16 + lr + (qq & 1) * 8;
        uint32_t off = row * TS + (qq >> 1) * 16;
        bHiA[p] = sb + SM_B_HI + off;
        bLoA[p] = sb + SM_B_LO + off;
    }

    int glr = tid >> 2;
    int glj = tid & 3;

    for (int c = 0; c < EE / KC; ++c) {
        int kc = c * KC;
        #pragma unroll
        for (int it = 0; it < 2; ++it) {
            int r = glr + it * 64;
            uint32_t so = r * TS + glj * 16;
            size_t ga = (size_t)(m0 + r) * EE + kc + glj * 8;
            size_t gb = (size_t)(n0 + r) * EE + kc + glj * 8;
            *(uint4*)(smem + SM_A_HI + so) = *(const uint4*)(Ahi + ga);
            *(uint4*)(smem + SM_A_LO + so) = *(const uint4*)(Alo + ga);
            *(uint4*)(smem + SM_B_HI + so) = *(const uint4*)(Whi + gb);
            *(uint4*)(smem + SM_B_LO + so) = *(const uint4*)(Wlo + gb);
        }
        __syncthreads();

        #pragma unroll
        for (int ks = 0; ks < 2; ++ks) {
            uint32_t koB = ks * 32;
            uint32_t aH[4][4], bH[2][4];
            #pragma unroll
            for (int mt = 0; mt < 4; ++mt) ldsm4(aH[mt], aHiA[mt] + koB);
            #pragma unroll
            for (int p = 0; p < 2; ++p) ldsm4(bH[p], bHiA[p] + koB);
            #pragma unroll
            for (int mt = 0; mt < 4; ++mt)
                #pragma unroll
                for (int nt = 0; nt < 4; ++nt)
                    mma16816(acc[mt][nt], aH[mt], bH[nt >> 1][nt & 1], bH[nt >> 1][(nt & 1) + 2]);
            {
                uint32_t bL[2][4];
                #pragma unroll
                for (int p = 0; p < 2; ++p) ldsm4(bL[p], bLoA[p] + koB);
                #pragma unroll
                for (int mt = 0; mt < 4; ++mt)
                    #pragma unroll
                    for (int nt = 0; nt < 4; ++nt)
                        mma16816(acc[mt][nt], aH[mt], bL[nt >> 1][nt & 1], bL[nt >> 1][(nt & 1) + 2]);
            }
            {
                uint32_t aL[4][4];
                #pragma unroll
                for (int mt = 0; mt < 4; ++mt) ldsm4(aL[mt], aLoA[mt] + koB);
                #pragma unroll
                for (int mt = 0; mt < 4; ++mt)
                    #pragma unroll
                    for (int nt = 0; nt < 4; ++nt)
                        mma16816(acc[mt][nt], aL[mt], bH[nt >> 1][nt & 1], bH[nt >> 1][(nt & 1) + 2]);
            }
        }
        __syncthreads();
    }

    int gid = lane >> 2;
    int tig = lane & 3;
    #pragma unroll
    for (int nt = 0; nt < 4; ++nt) {
        int col = n0 + wn * 32 + nt * 8 + tig * 2;
        float b0 = bias[col], b1 = bias[col + 1];
        #pragma unroll
        for (int mt = 0; mt < 4; ++mt) {
            int row = m0 + wm * 64 + mt * 16 + gid;
            float v0 = alpha * (acc[mt][nt][0] + b0);
            float v1 = alpha * (acc[mt][nt][1] + b1);
            float v2 = alpha * (acc[mt][nt][2] + b0);
            float v3 = alpha * (acc[mt][nt][3] + b1);
            if (SPLIT) {
                uint32_t h0 = pack_hi2(v0, v1);
                uint32_t l0 = pack_lo2(v0, v1, h0);
                uint32_t h1 = pack_hi2(v2, v3);
                uint32_t l1 = pack_lo2(v2, v3, h1);
                *(uint32_t*)&Chi[(size_t)row * EE + col] = h0;
                *(uint32_t*)&Clo[(size_t)row * EE + col] = l0;
                *(uint32_t*)&Chi[(size_t)(row + 8) * EE + col] = h1;
                *(uint32_t*)&Clo[(size_t)(row + 8) * EE + col] = l1;
            } else {
                float2 w0 = {v0, v1}, w1 = {v2, v3};
                *(float2*)&C[(size_t)row * EE + col] = w0;
                *(float2*)&C[(size_t)(row + 8) * EE + col] = w1;
            }
        }
    }
}

// ---------------- fused attention (flash-style, mma.sync bf16-split) ----------------
// CTA: 128 q rows, 8 warps (16 rows each). Key tile 64. Scores in fragments.
#define ATS 144     // smem row stride bytes (64 bf16 = 128B data + 16B pad)
#define SMK_HI 0
#define SMK_LO 9216
#define SMV_HI 18432
#define SMV_LO 27648
#define SM_MSK 36864

__global__ __launch_bounds__(256)
void attention_mma_kernel(const float* __restrict__ attn_bias,
                          const float* __restrict__ attn_mask)
{
    __shared__ __align__(16) char sm[36864 + 256 + 16];
    uint32_t sb = smem_u32(sm);
    float* maskS = (float*)(sm + SM_MSK);

    int tid = threadIdx.x;
    int wid = tid >> 5;
    int lane = tid & 31;
    int gid = lane >> 2;
    int tig = lane & 3;
    int lr = lane & 7;
    int qq = lane >> 3;
    int bh = blockIdx.y;
    int b = bh >> 4, h = bh & 15;
    int q0 = blockIdx.x * 128;
    int wq = wid * 16;

    // ---- stage Q tile (128x64 hi+lo) and extract fragments ----
    #pragma unroll
    for (int i = 0; i < 4; ++i) {
        int v = tid + i * 256;          // 0..1023
        int r = v >> 3;
        int j = v & 7;
        size_t ga = (size_t)(b * SS + q0 + r) * EE + h * DD + j * 8;
        *(uint4*)(sm + r * ATS + j * 16) = *(const uint4*)(g_Qhi + ga);
        *(uint4*)(sm + 18432 + r * ATS + j * 16) = *(const uint4*)(g_Qlo + ga);
    }
    __syncthreads();

    uint32_t aQh[4][4], aQl[4][4];
    {
        uint32_t base = (uint32_t)((wq + lr + (qq & 1) * 8) * ATS + (qq >> 1) * 16);
        #pragma unroll
        for (int kc = 0; kc < 4; ++kc) {
            ldsm4(aQh[kc], sb + base + kc * 32);
            ldsm4(aQl[kc], sb + 18432 + base + kc * 32);
        }
    }
    __syncthreads();

    float o[8][4];
    #pragma unroll
    for (int nt = 0; nt < 8; ++nt)
        #pragma unroll
        for (int k = 0; k < 4; ++k) o[nt][k] = 0.0f;
    float m0r = -INFINITY, m1r = -INFINITY, l0r = 0.0f, l1r = 0.0f;

    int qr0 = q0 + wq + gid;
    const float* biasRow0 = attn_bias + ((size_t)(b * HH + h) * SS + qr0) * SS;
    const float* biasRow1 = biasRow0 + 8 * SS;
    const float* amRow0 = attn_mask + (size_t)qr0 * SS;
    const float* amRow1 = amRow0 + 8 * SS;

    // K-fragment smem base
    uint32_t kfb = (uint32_t)((lr + (qq & 1) * 8) * ATS + (qq >> 1) * 16);
    // V-fragment (trans) lane map
    int vkey = ((lane >> 3) & 1) * 8 + lr;
    int vd = (lane >> 4) * 8;

    for (int k0 = 0; k0 < SS; k0 += 64) {
        // ---- load K/V tiles (hi+lo) ----
        #pragma unroll
        for (int i = 0; i < 8; ++i) {
            int v = tid + i * 256;      // 0..2047
            int arr = v >> 9;
            int rem = v & 511;
            int r = rem >> 3;
            int j = rem & 7;
            size_t ga = (size_t)(b * SS + k0 + r) * EE + h * DD + j * 8;
            const __nv_bfloat16* src = (arr == 0) ? g_Khi : (arr == 1) ? g_Klo
                                    : (arr == 2) ? g_Vhi : g_Vlo;
            *(uint4*)(sm + arr * 9216 + r * ATS + j * 16) = *(const uint4*)(src + ga);
        }
        if (tid < 64) maskS[tid] = g_maskflag[b * SS + k0 + tid];
        __syncthreads();

        // ---- S = Q K^T (3-term split) ----
        float s[8][4];
        #pragma unroll
        for (int nt = 0; nt < 8; ++nt)
            #pragma unroll
            for (int k = 0; k < 4; ++k) s[nt][k] = 0.0f;

        #pragma unroll
        for (int kc = 0; kc < 4; ++kc) {
            uint32_t koB = kc * 32;
            uint32_t bKh[4][4];
            #pragma unroll
            for (int ng = 0; ng < 4; ++ng)
                ldsm4(bKh[ng], sb + SMK_HI + (uint32_t)(ng * 16 * ATS) + kfb + koB);
            #pragma unroll
            for (int nt = 0; nt < 8; ++nt)
                mma16816(s[nt], aQh[kc], bKh[nt >> 1][nt & 1], bKh[nt >> 1][(nt & 1) + 2]);
            {
                uint32_t bKl[4][4];
                #pragma unroll
                for (int ng = 0; ng < 4; ++ng)
                    ldsm4(bKl[ng], sb + SMK_LO + (uint32_t)(ng * 16 * ATS) + kfb + koB);
                #pragma unroll
                for (int nt = 0; nt < 8; ++nt)
                    mma16816(s[nt], aQh[kc], bKl[nt >> 1][nt & 1], bKl[nt >> 1][(nt & 1) + 2]);
            }
            #pragma unroll
            for (int nt = 0; nt < 8; ++nt)
                mma16816(s[nt], aQl[kc], bKh[nt >> 1][nt & 1], bKh[nt >> 1][(nt & 1) + 2]);
        }

        // ---- bias + attn_mask + padding mask ----
        #pragma unroll
        for (int nt = 0; nt < 8; ++nt) {
            int col = nt * 8 + tig * 2;
            float2 bb0 = *(const float2*)&biasRow0[k0 + col];
            float2 bb1 = *(const float2*)&biasRow1[k0 + col];
            float2 am0 = *(const float2*)&amRow0[k0 + col];
            float2 am1 = *(const float2*)&amRow1[k0 + col];
            float mf0 = maskS[col], mf1 = maskS[col + 1];
            s[nt][0] = (mf0 > 0.5f) ? NEG_INF : s[nt][0] + bb0.x + am0.x;
            s[nt][1] = (mf1 > 0.5f) ? NEG_INF : s[nt][1] + bb0.y + am0.y;
            s[nt][2] = (mf0 > 0.5f) ? NEG_INF : s[nt][2] + bb1.x + am1.x;
            s[nt][3] = (mf1 > 0.5f) ? NEG_INF : s[nt][3] + bb1.y + am1.y;
        }

        // ---- online softmax (rows gid and gid+8) ----
        float mx0 = -INFINITY, mx1 = -INFINITY;
        #pragma unroll
        for (int nt = 0; nt < 8; ++nt) {
            mx0 = fmaxf(mx0, fmaxf(s[nt][0], s[nt][1]));
            mx1 = fmaxf(mx1, fmaxf(s[nt][2], s[nt][3]));
        }
        mx0 = fmaxf(mx0, __shfl_xor_sync(0xffffffffu, mx0, 1));
        mx0 = fmaxf(mx0, __shfl_xor_sync(0xffffffffu, mx0, 2));
        mx1 = fmaxf(mx1, __shfl_xor_sync(0xffffffffu, mx1, 1));
        mx1 = fmaxf(mx1, __shfl_xor_sync(0xffffffffu, mx1, 2));
        float mn0 = fmaxf(m0r, mx0), mn1 = fmaxf(m1r, mx1);
        float sc0 = __expf(m0r - mn0), sc1 = __expf(m1r - mn1);
        float rs0 = 0.0f, rs1 = 0.0f;
        #pragma unroll
        for (int nt = 0; nt < 8; ++nt) {
            s[nt][0] = __expf(s[nt][0] - mn0);
            s[nt][1] = __expf(s[nt][1] - mn0);
            s[nt][2] = __expf(s[nt][2] - mn1);
            s[nt][3] = __expf(s[nt][3] - mn1);
            rs0 += s[nt][0] + s[nt][1];
            rs1 += s[nt][2] + s[nt][3];
        }
        rs0 += __shfl_xor_sync(0xffffffffu, rs0, 1);
        rs0 += __shfl_xor_sync(0xffffffffu, rs0, 2);
        rs1 += __shfl_xor_sync(0xffffffffu, rs1, 1);
        rs1 += __shfl_xor_sync(0xffffffffu, rs1, 2);
        l0r = l0r * sc0 + rs0;
        l1r = l1r * sc1 + rs1;
        m0r = mn0; m1r = mn1;
        #pragma unroll
        for (int nt = 0; nt < 8; ++nt) {
            o[nt][0] *= sc0; o[nt][1] *= sc0;
            o[nt][2] *= sc1; o[nt][3] *= sc1;
        }

        // ---- pack P hi/lo as A-fragments ----
        uint32_t ph[4][4], pl[4][4];
        #pragma unroll
        for (int kc = 0; kc < 4; ++kc) {
            int n0t = 2 * kc, n1t = 2 * kc + 1;
            ph[kc][0] = pack_hi2(s[n0t][0], s[n0t][1]);
            pl[kc][0] = pack_lo2(s[n0t][0], s[n0t][1], ph[kc][0]);
            ph[kc][1] = pack_hi2(s[n0t][2], s[n0t][3]);
            pl[kc][1] = pack_lo2(s[n0t][2], s[n0t][3], ph[kc][1]);
            ph[kc][2] = pack_hi2(s[n1t][0], s[n1t][1]);
            pl[kc][2] = pack_lo2(s[n1t][0], s[n1t][1], ph[kc][2]);
            ph[kc][3] = pack_hi2(s[n1t][2], s[n1t][3]);
            pl[kc][3] = pack_lo2(s[n1t][2], s[n1t][3], ph[kc][3]);
        }

        // ---- O += P V (3-term split), V via ldmatrix.trans ----
        #pragma unroll
        for (int kc = 0; kc < 4; ++kc) {
            uint32_t vh[4][4], vl[4][4];
            #pragma unroll
            for (int dg = 0; dg < 4; ++dg) {
                uint32_t off = (uint32_t)((kc * 16 + vkey) * ATS + (dg * 16 + vd) * 2);
                ldsm4t(vh[dg], sb + SMV_HI + off);
                ldsm4t(vl[dg], sb + SMV_LO + off);
            }
            #pragma unroll
            for (int nt = 0; nt < 8; ++nt) {
                int dg = nt >> 1, sub = (nt & 1) * 2;
                mma16816(o[nt], ph[kc], vh[dg][sub], vh[dg][sub + 1]);
                mma16816(o[nt], ph[kc], vl[dg][sub], vl[dg][sub + 1]);
                mma16816(o[nt], pl[kc], vh[dg][sub], vh[dg][sub + 1]);
            }
        }
        __syncthreads();
    }

    // ---- normalize + emit bf16 hi/lo split ----
    float inv0 = 1.0f / l0r, inv1 = 1.0f / l1r;
    size_t row0 = (size_t)(b * SS + qr0) * EE + h * DD;
    size_t row1 = row0 + 8 * EE;
    #pragma unroll
    for (int nt = 0; nt < 8; ++nt) {
        int col = nt * 8 + tig * 2;
        float v0 = o[nt][0] * inv0, v1 = o[nt][1] * inv0;
        float v2 = o[nt][2] * inv1, v3 = o[nt][3] * inv1;
        uint32_t h0 = pack_hi2(v0, v1);
        uint32_t l0 = pack_lo2(v0, v1, h0);
        uint32_t h1 = pack_hi2(v2, v3);
        uint32_t l1 = pack_lo2(v2, v3, h1);
        *(uint32_t*)&g_AThi[row0 + col] = h0;
        *(uint32_t*)&g_ATlo[row0 + col] = l0;
        *(uint32_t*)&g_AThi[row1 + col] = h1;
        *(uint32_t*)&g_ATlo[row1 + col] = l1;
    }
}

// ---------------- launch ----------------
extern "C" void kernel_launch(void* const* d_in, const int* in_sizes, int n_in,
                              void* d_out, int out_size) {
    const float* query     = (const float*)d_in[0];
    const float* attn_bias = (const float*)d_in[3];
    const void*  kpm       = d_in[4];
    const float* attn_mask = (const float*)d_in[5];
    const float* Wq = (const float*)d_in[9];
    const float* bq = (const float*)d_in[10];
    const float* Wk = (const float*)d_in[11];
    const float* bk = (const float*)d_in[12];
    const float* Wv = (const float*)d_in[13];
    const float* bv = (const float*)d_in[14];
    const float* Wo = (const float*)d_in[15];
    const float* bo = (const float*)d_in[16];
    float* out = (float*)d_out;

    __nv_bfloat16 *gXhi, *gXlo, *gQhi, *gQlo, *gKhi, *gKlo, *gVhi, *gVlo,
                  *gAThi, *gATlo, *gWhi, *gWlo;
    cudaGetSymbolAddress((void**)&gXhi, g_Xhi);
    cudaGetSymbolAddress((void**)&gXlo, g_Xlo);
    cudaGetSymbolAddress((void**)&gQhi, g_Qhi);
    cudaGetSymbolAddress((void**)&gQlo, g_Qlo);
    cudaGetSymbolAddress((void**)&gKhi, g_Khi);
    cudaGetSymbolAddress((void**)&gKlo, g_Klo);
    cudaGetSymbolAddress((void**)&gVhi, g_Vhi);
    cudaGetSymbolAddress((void**)&gVlo, g_Vlo);
    cudaGetSymbolAddress((void**)&gAThi, g_AThi);
    cudaGetSymbolAddress((void**)&gATlo, g_ATlo);
    cudaGetSymbolAddress((void**)&gWhi, g_Whi);
    cudaGetSymbolAddress((void**)&gWlo, g_Wlo);

    const int nq4 = BB * SS * EE / 4;
    const int nw4 = EE * EE / 4;
    split_kernel<<<(nq4 + 255) / 256, 256>>>(query, gXhi, gXlo, nq4);
    split_kernel<<<(nw4 + 255) / 256, 256>>>(Wq, gWhi + 0 * (size_t)EE * EE, gWlo + 0 * (size_t)EE * EE, nw4);
    split_kernel<<<(nw4 + 255) / 256, 256>>>(Wk, gWhi + 1 * (size_t)EE * EE, gWlo + 1 * (size_t)EE * EE, nw4);
    split_kernel<<<(nw4 + 255) / 256, 256>>>(Wv, gWhi + 2 * (size_t)EE * EE, gWlo + 2 * (size_t)EE * EE, nw4);
    split_kernel<<<(nw4 + 255) / 256, 256>>>(Wo, gWhi + 3 * (size_t)EE * EE, gWlo + 3 * (size_t)EE * EE, nw4);

    detect_mask_kernel<<<1, 256>>>(kpm);
    expand_mask_kernel<<<(BB * SS + 255) / 256, 256>>>(kpm);

    dim3 ggrid(EE / 128, BB * SS / 128);   // (8, 64)
    const float scaling = 0.125f;          // D^-0.5

    gemm_mma_kernel<true><<<ggrid, 256>>>(gXhi, gXlo,
        gWhi + 0 * (size_t)EE * EE, gWlo + 0 * (size_t)EE * EE, bq,
        nullptr, gQhi, gQlo, scaling);
    gemm_mma_kernel<true><<<ggrid, 256>>>(gXhi, gXlo,
        gWhi + 1 * (size_t)EE * EE, gWlo + 1 * (size_t)EE * EE, bk,
        nullptr, gKhi, gKlo, 1.0f);
    gemm_mma_kernel<true><<<ggrid, 256>>>(gXhi, gXlo,
        gWhi + 2 * (size_t)EE * EE, gWlo + 2 * (size_t)EE * EE, bv,
        nullptr, gVhi, gVlo, 1.0f);

    attention_mma_kernel<<<dim3(SS / 128, BB * HH), 256>>>(attn_bias, attn_mask);

    gemm_mma_kernel<false><<<ggrid, 256>>>(gAThi, gATlo,
        gWhi + 3 * (size_t)EE * EE, gWlo + 3 * (size_t)EE * EE, bo,
        out, nullptr, nullptr, 1.0f);
}